// round 17
// baseline (speedup 1.0000x reference)
#include <cuda_runtime.h>
#include <math_constants.h>
#include <cstdint>

// Shapes: V=1024 fixed; B,L,T from in_sizes. Sized for B<=64, T<=1024, S<=256.
#define VOCAB      1024
#define MAXB       64
#define MAXTP      1056          // padded T rows (T + 32 slack)
#define SPC        128           // compact row: [0]=blank, [4+i]=label i, pad 0
#define NGRP       5             // ring groups (8 rows each)
#define RING       (NGRP * 8)    // 40 rows = 20 KB
#define NSM        148           // one-wave grid (GB300 has 152 >= 148)
#define THREADS    512           // 16 warps per CTA
#define PWARPS     16
#define FULLMASK   0xffffffffu

#define LOG2E_F 1.4426950408889634f
#define LN2_F   0.6931471805599453f

typedef unsigned long long ull;

static __device__ __forceinline__ float fex2(float x) {
    float y; asm("ex2.approx.f32 %0, %1;" : "=f"(y) : "f"(x)); return y;
}

#define CP16(sm, gp) \
    asm volatile("cp.async.cg.shared.global [%0], [%1], 16;" :: "r"(sm), "l"(gp))
#define CP_COMMIT() \
    asm volatile("cp.async.commit_group;" ::: "memory")
#define CP_WAIT_2() \
    asm volatile("cp.async.wait_group 2;" ::: "memory")
#define CP_WAIT_ALL() \
    asm volatile("cp.async.wait_all;" ::: "memory")

// Scratch
__device__ float         g_p[(size_t)MAXB * MAXTP * SPC];
__device__ unsigned char g_flag[(size_t)MAXB * MAXTP];
__device__ float         g_loss[MAXB];

static __device__ __forceinline__ ull ld_flags_acq(const unsigned char* p) {
    ull v;
    asm volatile("ld.acquire.gpu.global.b64 %0, [%1];" : "=l"(v) : "l"(p) : "memory");
    return v;
}

// ---------------------------------------------------------------------------
// Kernel 0: reset flags. Rows t < T start 0; pad rows preset to 1.
// ---------------------------------------------------------------------------
__global__ void init_flags_kernel(int B, int T, int TP)
{
    int i = blockIdx.x * 256 + threadIdx.x;
    if (i < B * TP) {
        int t = i % TP;
        g_flag[i] = (t < T) ? 0 : 1;
    }
}

// ---------------------------------------------------------------------------
// Kernel 1 (fused, ONE WAVE of 148 CTAs — dedicated SMs per role):
//   blockIdx <  B : CONSUMER — warp 0 runs the R16 scan on a private SM.
//   blockIdx >= B : PRODUCER — 16 warps, one softmax row each, t-major order.
// ---------------------------------------------------------------------------
__global__ void __launch_bounds__(THREADS, 1)
fused_kernel(const float* __restrict__ pred,
             const int*   __restrict__ plen,
             const int*   __restrict__ gt,
             const int*   __restrict__ gtl,
             int B, int T, int TP, int L, int S, int NT, int NPROD)
{
    // ======================= PRODUCER =======================
    if ((int)blockIdx.x >= B) {
        const int wid  = threadIdx.x >> 5;
        const int lane = threadIdx.x & 31;
        const int stride = NPROD * PWARPS;
        for (int rank = ((int)blockIdx.x - B) * PWARPS + wid; rank < NT; rank += stride) {
            const int t = rank / B;               // t-major production order
            const int b = rank - t * B;
            const float* __restrict__ p = pred + ((size_t)b * T + t) * VOCAB;

            float4 v[8];
            #pragma unroll
            for (int k = 0; k < 8; k++)
                v[k] = *reinterpret_cast<const float4*>(p + lane * 4 + k * 128);

            float mx = -CUDART_INF_F;
            #pragma unroll
            for (int k = 0; k < 8; k++)
                mx = fmaxf(mx, fmaxf(fmaxf(v[k].x, v[k].y), fmaxf(v[k].z, v[k].w)));
            #pragma unroll
            for (int o = 16; o; o >>= 1)
                mx = fmaxf(mx, __shfl_xor_sync(FULLMASK, mx, o));
            const float c = mx * LOG2E_F;

            float sum = 0.f;
            #pragma unroll
            for (int k = 0; k < 8; k++) {
                sum += fex2(fmaf(v[k].x, LOG2E_F, -c)) + fex2(fmaf(v[k].y, LOG2E_F, -c))
                     + fex2(fmaf(v[k].z, LOG2E_F, -c)) + fex2(fmaf(v[k].w, LOG2E_F, -c));
            }
            #pragma unroll
            for (int o = 16; o; o >>= 1)
                sum += __shfl_xor_sync(FULLMASK, sum, o);
            const float inv = __frcp_rn(sum);

            float* __restrict__ out = g_p + ((size_t)b * TP + t) * SPC;
            const int* __restrict__ gtb = gt + (size_t)b * L;

            float4 w = make_float4(0.f, 0.f, 0.f, 0.f);
            int ofs;
            if (lane < 25) {
                ofs = 4 + 4 * lane;
                #pragma unroll
                for (int k = 0; k < 4; k++) {
                    int j = 4 * lane + k;
                    float r = 0.f;
                    if (j < L) {
                        int lab = gtb[j];
                        r = fex2(fmaf(__ldg(p + lab), LOG2E_F, -c)) * inv;
                    }
                    (&w.x)[k] = r;
                }
            } else if (lane < 31) {
                ofs = 4 + 4 * lane;                 // zero pads
            } else {
                ofs = 0;                            // blank scalar in .x
                w.x = fex2(fmaf(__ldg(p), LOG2E_F, -c)) * inv;
            }
            *reinterpret_cast<float4*>(out + ofs) = w;

            __syncwarp();
            if (lane == 0) {
                __threadfence();
                asm volatile("st.relaxed.gpu.global.u8 [%0], %1;"
                             :: "l"(g_flag + (size_t)b * TP + t), "h"((unsigned short)1)
                             : "memory");
            }
        }
        return;
    }

    // ======================= CONSUMER =======================
    __shared__ float ring[RING][SPC];     // 20 KB
    if (threadIdx.x >= 32) return;        // single scan warp

    const int b    = blockIdx.x;
    const int lane = threadIdx.x;
    const int ilen = min(plen[b], T);
    const int tl   = gtl[b];
    const float* __restrict__ Pb = g_p + (size_t)b * TP * SPC;
    const int* __restrict__ gtb = gt + (size_t)b * L;
    const unsigned char* flg = g_flag + (size_t)b * TP;
    const unsigned int rb =
        (unsigned int)__cvta_generic_to_shared(ring) + (unsigned int)(lane * 16);
    const int lv_ofs = (lane < 31) ? (4 + 4 * lane) : 124;
    const ull RDY = 0x0101010101010101ull;

    // Skip masks for the 4 odd (label) states; even states never skip.
    float m1, m3, m5, m7;
    {
        float mm[4];
        #pragma unroll
        for (int jj = 0; jj < 4; jj++) {
            int s = lane * 8 + 2 * jj + 1;
            float v = 0.f;
            if (s >= 2 && s < S) {
                int lab = gtb[s >> 1], lm2 = gtb[(s >> 1) - 1];
                v = (lab != 0 && lab != lm2) ? 1.f : 0.f;
            }
            mm[jj] = v;
        }
        m1 = mm[0]; m3 = mm[1]; m5 = mm[2]; m7 = mm[3];
    }

    int   El = 0;
    float f  = (lane == 0) ? 0.f : 1.f;
    const int nsteps = ilen - 1;

#define CTC_STEP(LV, PB)                                                    \
    do {                                                                     \
        float u7  = __shfl_up_sync(FULLMASK, a[7], 1);                       \
        float u7f = u7 * f;                                                  \
        float n0 = (a[0] + u7f)                * (PB);                       \
        float n1 = fmaf(m1, u7f,  a[1] + a[0]) * (LV).x;                     \
        float n2 = (a[2] + a[1])               * (PB);                       \
        float n3 = fmaf(m3, a[1], a[3] + a[2]) * (LV).y;                     \
        float n4 = (a[4] + a[3])               * (PB);                       \
        float n5 = fmaf(m5, a[3], a[5] + a[4]) * (LV).z;                     \
        float n6 = (a[6] + a[5])               * (PB);                       \
        float n7 = fmaf(m7, a[5], a[7] + a[6]) * (LV).w;                     \
        a[0]=n0; a[1]=n1; a[2]=n2; a[3]=n3; a[4]=n4; a[5]=n5; a[6]=n6; a[7]=n7; \
    } while (0)

#define CTC_RENORM()                                                        \
    do {                                                                     \
        float mx = fmaxf(fmaxf(fmaxf(a[0], a[1]), fmaxf(a[2], a[3])),       \
                         fmaxf(fmaxf(a[4], a[5]), fmaxf(a[6], a[7])));       \
        bool nz = (mx > 0.f);                                                \
        int  e  = nz ? ((__float_as_int(mx) >> 23) - 127) : 0;               \
        int  Elp = El + e;                                                   \
        int  Eleft = __shfl_up_sync(FULLMASK, Elp, 1);                       \
        if (!nz && lane > 0) Elp = Eleft;                                    \
        if (nz) {                                                            \
            float sc = __int_as_float((127 - e) << 23);                      \
            _Pragma("unroll")                                                \
            for (int j = 0; j < 8; j++) a[j] *= sc;                          \
        }                                                                    \
        El = Elp;                                                            \
        int El2 = __shfl_up_sync(FULLMASK, El, 1);                           \
        int dE  = El2 - El;                                                  \
        if (lane == 0 || dE < -126) f = 0.f;                                 \
        else f = __int_as_float((min(dE, 126) + 127) << 23);                 \
    } while (0)

#define LDROWS(LV, PB, SLOT)                                                \
    do {                                                                     \
        const float* rp_ = &ring[(SLOT)][0];                                 \
        (LV) = *reinterpret_cast<const float4*>(rp_ + lv_ofs);               \
        (PB) = rp_[0];                                                       \
    } while (0)

    // Prologue: gate + fill groups 0..3 (rows 0..31 -> slots 0..31).
    for (int g = 0; g < 4; g++) {
        while (ld_flags_acq(flg + g * 8) != RDY) { }
        const float* gp = Pb + (size_t)(g * 8) * SPC + lane * 4;
        #pragma unroll
        for (int r = 0; r < 8; r++) {
            CP16(rb + (unsigned int)((g * 8 + r) * (SPC * 4)), gp);
            gp += SPC;
        }
        CP_COMMIT();
    }
    ull nf = ld_flags_acq(flg + 32);       // flags for group 4
    CP_WAIT_2();                            // groups 0,1 landed

    // alpha(t=0) from ring slot 0.
    float a[8];
    #pragma unroll
    for (int j = 0; j < 8; j++) a[j] = 0.f;
    float4 lv; float pb;
    LDROWS(lv, pb, 0);
    if (lane == 0) {
        a[0] = pb;
        a[1] = (tl > 0) ? lv.x : 0.f;
    }

    // Initial partial block: steps t = 1..min(7, nsteps), rows 1..8.
    {
        int tlim0 = min(7, nsteps);
        if (nsteps >= 1) LDROWS(lv, pb, 1);
        for (int t = 1; t <= tlim0; t++) {
            float4 nlv; float npb;
            LDROWS(nlv, npb, t + 1);        // rows 2..8 -> slots 2..8 (landed)
            CTC_STEP(lv, pb);
            lv = nlv; pb = npb;
        }
        if (tlim0 == 7) CTC_RENORM();
    }

    // Mainloop: block g consumes rows 8g+1..8g+8, fills group g+3.
    int g = 1, cg = 1, fg = 4;              // group-slot counters (mod 5)
    for (; 8 * g + 7 <= nsteps; g++) {
        if (nf != RDY) {
            do { nf = ld_flags_acq(flg + (g + 3) * 8); } while (nf != RDY);
        }
        {
            const float* gp = Pb + (size_t)((g + 3) * 8) * SPC + lane * 4;
            #pragma unroll
            for (int r = 0; r < 8; r++) {
                CP16(rb + (unsigned int)((fg * 8 + r) * (SPC * 4)), gp);
                gp += SPC;
            }
            CP_COMMIT();
        }
        CP_WAIT_2();                        // group g+1 landed
        nf = ld_flags_acq(flg + (g + 4) * 8);

        int ng = (cg + 1 == NGRP) ? 0 : cg + 1;
        #pragma unroll
        for (int k = 0; k < 8; k++) {
            float4 nlv; float npb;
            int slot = (k < 7) ? (cg * 8 + k + 1) : (ng * 8);
            LDROWS(nlv, npb, slot);
            CTC_STEP(lv, pb);
            if (k == 7) CTC_RENORM();
            lv = nlv; pb = npb;
        }
        cg = ng; fg = (fg + 1 == NGRP) ? 0 : fg + 1;
    }
    // Tail: rows 8g..nsteps(+1) are filled & flag-gated already.
    if (8 * g <= nsteps) {
        CP_WAIT_ALL();
        int ng = (cg + 1 == NGRP) ? 0 : cg + 1;
        for (int t = 8 * g; t <= nsteps; t++) {
            float4 nlv; float npb;
            int k = t + 1 - 8 * g;          // 1..8
            int slot = (k < 8) ? (cg * 8 + k) : (ng * 8);
            LDROWS(nlv, npb, slot);
            CTC_STEP(lv, pb);
            lv = nlv; pb = npb;
        }
    }
#undef CTC_STEP
#undef CTC_RENORM
#undef LDROWS

    // end_ll over alpha[2*tl] and alpha[max(2*tl-1,0)]
    int s1 = 2 * tl;
    int s2 = (2 * tl - 1 > 0) ? (2 * tl - 1) : 0;
    int lane1 = s1 >> 3, slot1 = s1 & 7;
    int lane2 = s2 >> 3, slot2 = s2 & 7;
    float v1 = a[0], v2 = a[0];
    #pragma unroll
    for (int j = 1; j < 8; j++) { v1 = (slot1 == j) ? a[j] : v1;
                                  v2 = (slot2 == j) ? a[j] : v2; }
    int   E1 = __shfl_sync(FULLMASK, El, lane1);
    int   E2 = __shfl_sync(FULLMASK, El, lane2);
    v1 = __shfl_sync(FULLMASK, v1, lane1);
    v2 = __shfl_sync(FULLMASK, v2, lane2);

    if (lane == 0) {
        float l1 = (v1 > 0.f) ? (log2f(v1) + (float)E1) : -3.0e38f;
        float l2 = (v2 > 0.f) ? (log2f(v2) + (float)E2) : -3.0e38f;
        float mx = fmaxf(l1, l2);
        float loss;
        if (mx < -2.0e38f) {
            loss = 0.f;                    // zero_infinity
        } else {
            float tot2 = mx + log2f(exp2f(l1 - mx) + exp2f(l2 - mx));
            loss = -tot2 * LN2_F;
        }
        g_loss[b] = loss / (float)tl;
    }
}

// ---------------------------------------------------------------------------
// Kernel 2: deterministic batch-mean reduction (single warp).
// ---------------------------------------------------------------------------
__global__ void reduce_loss_kernel(float* __restrict__ out, int B)
{
    float v = 0.f;
    for (int i = threadIdx.x; i < B; i += 32) v += g_loss[i];
    #pragma unroll
    for (int o = 16; o; o >>= 1) v += __shfl_xor_sync(FULLMASK, v, o);
    if (threadIdx.x == 0) out[0] = v / (float)B;
}

// ---------------------------------------------------------------------------
extern "C" void kernel_launch(void* const* d_in, const int* in_sizes, int n_in,
                              void* d_out, int out_size)
{
    const float* pred = (const float*)d_in[0];
    const int*   plen = (const int*)d_in[1];
    const int*   gt   = (const int*)d_in[2];
    const int*   gtl  = (const int*)d_in[3];

    const int B  = in_sizes[1];
    const int L  = in_sizes[2] / B;
    const int T  = in_sizes[0] / (B * VOCAB);
    const int S  = 2 * L + 1;
    const int TP = T + 32;                 // padded rows (fill slack)
    const int NT = B * T;
    const int NPROD = NSM - B;             // producer CTAs (dedicated SMs)

    const int nflag = B * TP;
    init_flags_kernel<<<(nflag + 255) / 256, 256>>>(B, T, TP);

    fused_kernel<<<B + NPROD, THREADS>>>(pred, plen, gt, gtl,
                                         B, T, TP, L, S, NT, NPROD);

    reduce_loss_kernel<<<1, 32>>>((float*)d_out, B);
}